// round 7
// baseline (speedup 1.0000x reference)
#include <cuda_runtime.h>
#include <cuda_bf16.h>

// Problem constants (match reference)
#define MAX_LEN_SEQ 2048
#define T_PAD       2176   // MAX_LEN_PAD
#define MIN_SEG     32
#define S_          65     // segments per batch
#define B_          16
#define D_          128
#define R_          1040   // B_ * S_
#define W_          256

// Scratch (device globals; no allocation allowed)
__device__ int g_offset[R_];
__device__ int g_count[R_];
__device__ int g_rowstart[R_ + 1];
__device__ int g_L;

// ---------------------------------------------------------------------------
// K1: per batch, serial walk over its 65 segments. All 256 threads evaluate
// the mask for their w, __syncthreads_count gives the per-row masked count
// (mask is a prefix in w since floor(w/sc) is monotone). Offsets are the
// exclusive cumsum of len_seg within the batch (kept identically in every
// thread's registers).
// ---------------------------------------------------------------------------
__global__ void k_count(const float* __restrict__ scales,
                        const int*   __restrict__ len_seq,
                        const int*   __restrict__ len_seg_raw) {
    int b = blockIdx.x;
    int w = threadIdx.x;
    float lenq_m1 = (float)len_seq[b] - 1.0f;
    int off = 0;
    #pragma unroll 1
    for (int s = 0; s < S_; s++) {
        int r = b * S_ + s;
        int len_seg = len_seg_raw[r] + MIN_SEG;
        float sc = scales[r] + 0.5f;
        float idx_scaled = (float)w / sc;      // IEEE fp32 div, matches jax
        float idx_fl = floorf(idx_scaled);
        bool m = (idx_fl < ((float)len_seg - 1.0f)) &&
                 ((idx_fl + (float)off) < lenq_m1);
        int cnt = __syncthreads_count(m ? 1 : 0);
        if (w == 0) { g_count[r] = cnt; g_offset[r] = off; }
        off += len_seg;
    }
}

// ---------------------------------------------------------------------------
// K2: exclusive scan of g_count[0..R_-1] -> g_rowstart, total, L.
// One block; 32 lanes each own a 33-row chunk (32*33 = 1056 >= 1040).
// ---------------------------------------------------------------------------
__global__ void k_scan() {
    __shared__ int sh[R_];
    int tid = threadIdx.x;
    for (int i = tid; i < R_; i += blockDim.x) sh[i] = g_count[i];
    __syncthreads();
    if (tid < 32) {
        const int CH = 33;
        int base = tid * CH;
        int s = 0;
        #pragma unroll
        for (int j = 0; j < CH; j++) {
            int i = base + j;
            if (i < R_) s += sh[i];
        }
        // inclusive warp scan -> exclusive
        int incl = s;
        #pragma unroll
        for (int d = 1; d < 32; d <<= 1) {
            int v = __shfl_up_sync(0xffffffffu, incl, d);
            if (tid >= d) incl += v;
        }
        int run = incl - s;  // exclusive prefix of chunk sums
        #pragma unroll
        for (int j = 0; j < CH; j++) {
            int i = base + j;
            if (i < R_) { g_rowstart[i] = run; run += sh[i]; }
        }
        if (tid == 31) {
            g_rowstart[R_] = run;        // total
            g_L = run / B_;
        }
    }
}

// ---------------------------------------------------------------------------
// K3: one warp per output row (b, t). Invert the global compaction:
//   g = b*L + t; find r = max { r : rowstart[r] <= g }; w = g - rowstart[r].
// Recompute lam / source index with the same fp32 ops and lerp two 512B rows.
// ---------------------------------------------------------------------------
__global__ __launch_bounds__(256) void k_gather(const float* __restrict__ x,
                                                const float* __restrict__ scales,
                                                float* __restrict__ out) {
    int warp = blockIdx.x * (blockDim.x >> 5) + (threadIdx.x >> 5);
    int lane = threadIdx.x & 31;
    if (warp >= B_ * MAX_LEN_SEQ) return;
    int b = warp >> 11;          // / 2048
    int t = warp & (MAX_LEN_SEQ - 1);

    float4* orow = reinterpret_cast<float4*>(out + (size_t)warp * D_);
    int L = g_L;
    if (t >= L) { orow[lane] = make_float4(0.f, 0.f, 0.f, 0.f); return; }

    int g = b * L + t;
    // binary search: largest r with rowstart[r] <= g  (rowstart[0]=0 <= g)
    int lo = 0, hi = R_;
    #pragma unroll 1
    while (hi - lo > 1) {
        int mid = (lo + hi) >> 1;
        if (__ldg(&g_rowstart[mid]) <= g) lo = mid; else hi = mid;
    }
    int r = lo;
    int w = g - __ldg(&g_rowstart[r]);

    float sc = __ldg(&scales[r]) + 0.5f;
    float idx_scaled = (float)w / sc;
    float idx_fl = floorf(idx_scaled);
    float lam = idx_scaled - idx_fl;
    int off = __ldg(&g_offset[r]);
    int i_fl = (int)idx_fl + off;          // >= 0 always
    if (i_fl > T_PAD - 1) i_fl = T_PAD - 1;
    int i_cl = min(i_fl + 1, T_PAD - 1);
    int bsrc = r / S_;

    const float4* pa = reinterpret_cast<const float4*>(x + ((size_t)bsrc * T_PAD + i_fl) * D_);
    const float4* pc = reinterpret_cast<const float4*>(x + ((size_t)bsrc * T_PAD + i_cl) * D_);
    float4 va = __ldg(&pa[lane]);
    float4 vc = __ldg(&pc[lane]);
    float om = 1.0f - lam;
    float4 vy;
    vy.x = om * va.x + lam * vc.x;
    vy.y = om * va.y + lam * vc.y;
    vy.z = om * va.z + lam * vc.z;
    vy.w = om * va.w + lam * vc.w;
    orow[lane] = vy;
}

extern "C" void kernel_launch(void* const* d_in, const int* in_sizes, int n_in,
                              void* d_out, int out_size) {
    const float* x           = (const float*)d_in[0];
    const float* scales      = (const float*)d_in[1];
    const int*   len_seq     = (const int*)d_in[2];
    const int*   len_seg_raw = (const int*)d_in[3];
    float* out = (float*)d_out;

    k_count<<<B_, W_>>>(scales, len_seq, len_seg_raw);
    k_scan<<<1, 1024>>>();
    int rows = B_ * MAX_LEN_SEQ;             // 32768 output rows
    int warps_per_block = 8;                  // 256 threads
    int grid = rows / warps_per_block;        // 4096
    k_gather<<<grid, 256>>>(x, scales, out);
}

// round 8
// speedup vs baseline: 2.0711x; 2.0711x over previous
#include <cuda_runtime.h>
#include <cuda_bf16.h>

#define MAX_LEN_SEQ 2048
#define T_PAD       2176
#define MIN_SEG     32
#define S_          65
#define B_          16
#define D_          128
#define R_          1040
#define W_          256

__device__ int g_offset[R_];
__device__ int g_count[R_];
__device__ int g_rowstart[R_ + 1];
__device__ int g_L;

// ---------------------------------------------------------------------------
// K1: one block per batch, one thread per segment row.
// Mask is a prefix in w (floor(w/sc) monotone in w under IEEE fp32 div),
// so count = first w in [0,256] with floorf(w/sc) >= lim, found by binary
// search using the EXACT same fp32 expression as the reference.
// lim = min(len_seg-1, len_seq-1-off): all values are small integers, exact
// in fp32, so the float compares in the reference reduce to this int compare.
// ---------------------------------------------------------------------------
__global__ void k_count(const float* __restrict__ scales,
                        const int*   __restrict__ len_seq,
                        const int*   __restrict__ len_seg_raw) {
    __shared__ int sh_len[S_];
    int b = blockIdx.x;
    int tid = threadIdx.x;
    if (tid < S_) sh_len[tid] = len_seg_raw[b * S_ + tid] + MIN_SEG;
    __syncthreads();
    if (tid < S_) {
        int off = 0;
        #pragma unroll 4
        for (int j = 0; j < tid; j++) off += sh_len[j];   // shared broadcast reads
        int len_seg = sh_len[tid];
        int lim = min(len_seg - 1, len_seq[b] - 1 - off);
        int r = b * S_ + tid;
        float sc = scales[r] + 0.5f;
        float limf = (float)lim;
        // first w with floorf(w/sc) >= limf  (pred monotone nonincreasing)
        int lo = 0, hi = W_;
        #pragma unroll 1
        while (lo < hi) {
            int mid = (lo + hi) >> 1;
            if (floorf((float)mid / sc) < limf) lo = mid + 1; else hi = mid;
        }
        g_count[r]  = lo;   // lo==0 automatically when lim<=0
        g_offset[r] = off;
    }
}

// ---------------------------------------------------------------------------
// K2: exclusive scan of g_count -> g_rowstart, total, L. One block.
// ---------------------------------------------------------------------------
__global__ void k_scan() {
    __shared__ int sh[R_];
    int tid = threadIdx.x;
    for (int i = tid; i < R_; i += blockDim.x) sh[i] = g_count[i];
    __syncthreads();
    if (tid < 32) {
        const int CH = 33;
        int base = tid * CH;
        int s = 0;
        #pragma unroll
        for (int j = 0; j < CH; j++) {
            int i = base + j;
            if (i < R_) s += sh[i];
        }
        int incl = s;
        #pragma unroll
        for (int d = 1; d < 32; d <<= 1) {
            int v = __shfl_up_sync(0xffffffffu, incl, d);
            if (tid >= d) incl += v;
        }
        int run = incl - s;
        #pragma unroll
        for (int j = 0; j < CH; j++) {
            int i = base + j;
            if (i < R_) { g_rowstart[i] = run; run += sh[i]; }
        }
        if (tid == 31) {
            g_rowstart[R_] = run;
            g_L = run / B_;
        }
    }
}

// ---------------------------------------------------------------------------
// K3: one warp per output row (b, t). Warp-parallel 2-round search of
// g_rowstart (stride-33 coarse probe + ballot, then 32-wide chunk probe +
// popcount) replaces the 11-step scalar binary search: 2 dependent loads.
// ---------------------------------------------------------------------------
__global__ __launch_bounds__(256) void k_gather(const float* __restrict__ x,
                                                const float* __restrict__ scales,
                                                float* __restrict__ out) {
    int warp = blockIdx.x * (blockDim.x >> 5) + (threadIdx.x >> 5);
    int lane = threadIdx.x & 31;
    if (warp >= B_ * MAX_LEN_SEQ) return;
    int b = warp >> 11;
    int t = warp & (MAX_LEN_SEQ - 1);

    float4* orow = reinterpret_cast<float4*>(out + (size_t)warp * D_);
    int L = g_L;
    if (t >= L) { orow[lane] = make_float4(0.f, 0.f, 0.f, 0.f); return; }

    int g = b * L + t;

    // round 1: coarse probe at stride 33 (lane*33 in [0,1023], always valid)
    int i1 = lane * 33;
    bool p1 = (__ldg(&g_rowstart[i1]) <= g);          // lane 0 always true
    unsigned m1 = __ballot_sync(0xffffffffu, p1);
    int base = (31 - __clz(m1)) * 33;
    // round 2: probe base+1 .. base+32; prefix of trues gives offset
    int i2 = base + 1 + lane;
    bool p2 = (i2 <= R_) && (__ldg(&g_rowstart[i2]) <= g);
    unsigned m2 = __ballot_sync(0xffffffffu, p2);
    int r = base + __popc(m2);

    int w = g - __ldg(&g_rowstart[r]);

    float sc = __ldg(&scales[r]) + 0.5f;
    float idx_scaled = (float)w / sc;
    float idx_fl = floorf(idx_scaled);
    float lam = idx_scaled - idx_fl;
    int i_fl = (int)idx_fl + __ldg(&g_offset[r]);
    if (i_fl > T_PAD - 1) i_fl = T_PAD - 1;
    int i_cl = min(i_fl + 1, T_PAD - 1);
    int bsrc = r / S_;

    const float4* pa = reinterpret_cast<const float4*>(x + ((size_t)bsrc * T_PAD + i_fl) * D_);
    const float4* pc = reinterpret_cast<const float4*>(x + ((size_t)bsrc * T_PAD + i_cl) * D_);
    float4 va = __ldg(&pa[lane]);
    float4 vc = __ldg(&pc[lane]);
    float om = 1.0f - lam;
    float4 vy;
    vy.x = om * va.x + lam * vc.x;
    vy.y = om * va.y + lam * vc.y;
    vy.z = om * va.z + lam * vc.z;
    vy.w = om * va.w + lam * vc.w;
    orow[lane] = vy;
}

extern "C" void kernel_launch(void* const* d_in, const int* in_sizes, int n_in,
                              void* d_out, int out_size) {
    const float* x           = (const float*)d_in[0];
    const float* scales      = (const float*)d_in[1];
    const int*   len_seq     = (const int*)d_in[2];
    const int*   len_seg_raw = (const int*)d_in[3];
    float* out = (float*)d_out;

    k_count<<<B_, 128>>>(scales, len_seq, len_seg_raw);
    k_scan<<<1, 1024>>>();
    k_gather<<<(B_ * MAX_LEN_SEQ) / 8, 256>>>(x, scales, out);
}